// round 9
// baseline (speedup 1.0000x reference)
#include <cuda_runtime.h>
#include <cstdint>

// CrossSpatialWindowAttention — fused tf32 mma, pre-swizzled weights,
// register-resident P (flash-style attention: scores->exp->shuffle-convert->AV
// entirely in registers). 512 threads, ~160KB smem, 1 CTA/SM.

namespace {

constexpr int IMG     = 256;
constexpr int CQ      = 96;
constexpr int CKV     = 192;
constexpr int NH      = 6;
constexpr int WIN     = 64;
constexpr int THREADS = 512;

// weight-fragment table (uint4): [nt][kk][lane]
constexpr int FK_OFF = 0;
constexpr int FV_OFF = 4608;
constexpr int FQ_OFF = 9216;
constexpr int FO_OFF = 11520;
constexpr int F_TOTAL = 13824;
__device__ uint4 gWF[F_TOTAL];

// leading dims: multiples of 4, ≡4 (mod 32)
constexpr int LD_X  = 196;
constexpr int LD_XQ = 100;
constexpr int LD_QK = 100;
constexpr int LD_VT = 68;
constexpr int LD_O  = 100;
constexpr int LD_F  = 68;

// smem offsets (floats)
constexpr int OFF_XKV = 0;        // 12544; later: F (6528)
constexpr int OFF_XQ  = 12544;    // 6400;  later: attn-out O
constexpr int OFF_Q   = 18944;    // 6400
constexpr int OFF_K   = 25344;    // 6400
constexpr int OFF_VT  = 31744;    // 6528
constexpr int OFF_BT  = 38272;    // 1350
constexpr int OFF_BQ  = 39622;
constexpr int OFF_BK  = 39718;
constexpr int OFF_BV  = 39814;
constexpr int OFF_BO  = 39910;
constexpr int SMEM_FLOATS = 40006;   // ~160 KB
constexpr int OFF_O  = OFF_XQ;
constexpr int OFF_F  = OFF_XKV;

__device__ __forceinline__ float to_tf32(float x) {
    float r; asm("cvt.rna.tf32.f32 %0, %1;" : "=f"(r) : "f"(x)); return r;
}

__device__ __forceinline__ uint32_t smem_u32(const void* p) {
    return (uint32_t)__cvta_generic_to_shared(p);
}

__device__ __forceinline__ void ldsm4(uint32_t r[4], uint32_t addr) {
    asm volatile("ldmatrix.sync.aligned.m8n8.x4.shared.b16 {%0,%1,%2,%3}, [%4];"
                 : "=r"(r[0]), "=r"(r[1]), "=r"(r[2]), "=r"(r[3]) : "r"(addr));
}

__device__ __forceinline__ void mma8(float c[4], const uint32_t a[4],
                                     uint32_t b0, uint32_t b1) {
    asm volatile("mma.sync.aligned.m16n8k8.row.col.f32.tf32.tf32.f32 "
                 "{%0,%1,%2,%3},{%4,%5,%6,%7},{%8,%9},{%0,%1,%2,%3};"
                 : "+f"(c[0]), "+f"(c[1]), "+f"(c[2]), "+f"(c[3])
                 : "r"(a[0]), "r"(a[1]), "r"(a[2]), "r"(a[3]), "r"(b0), "r"(b1));
}

__device__ __forceinline__ uint32_t a_lane_off(int m0, int lda, int lane) {
    const int row = m0 + (lane & 7) + ((lane >> 3) & 1) * 8;
    const int ko  = ((lane >> 4) & 1) * 4;
    return (uint32_t)(row * lda + ko);
}
__device__ __forceinline__ uint32_t b_lane_off(int n0, int ldb, int lane) {
    const int row = n0 + (lane & 7);
    const int ko  = ((lane >> 3) & 3) * 4;
    return (uint32_t)(row * ldb + ko);
}

// Convert scores C-fragment (4 regs, one m16n8 tile, rows g/g+8, cols kb+2tig..)
// into AV A-fragment (m16k8) via intra-quad shuffles; applies tf32 rounding.
__device__ __forceinline__ void cfrag_to_afrag(const float c[4], uint32_t a[4], int lane) {
    const int tig = lane & 3;
    const int s1 = (lane & ~3) | (tig >> 1);
    const int s2 = s1 + 2;
    const bool odd = (tig & 1);
    float v0 = __shfl_sync(0xffffffffu, c[0], s1);
    float v1 = __shfl_sync(0xffffffffu, c[1], s1);
    a[0] = __float_as_uint(to_tf32(odd ? v1 : v0));
    v0 = __shfl_sync(0xffffffffu, c[2], s1);
    v1 = __shfl_sync(0xffffffffu, c[3], s1);
    a[1] = __float_as_uint(to_tf32(odd ? v1 : v0));
    v0 = __shfl_sync(0xffffffffu, c[0], s2);
    v1 = __shfl_sync(0xffffffffu, c[1], s2);
    a[2] = __float_as_uint(to_tf32(odd ? v1 : v0));
    v0 = __shfl_sync(0xffffffffu, c[2], s2);
    v1 = __shfl_sync(0xffffffffu, c[3], s2);
    a[3] = __float_as_uint(to_tf32(odd ? v1 : v0));
}

// ---- prep: swizzle weights into mma-fragment order ----
__global__ void prep_kernel(const float* __restrict__ Wk, const float* __restrict__ Wv,
                            const float* __restrict__ Wq, const float* __restrict__ Wo) {
    const int idx = blockIdx.x * blockDim.x + threadIdx.x;
    if (idx >= F_TOTAL) return;
    const float* W; int KS2, f;
    if (idx < FV_OFF)      { W = Wk; KS2 = 12; f = idx; }
    else if (idx < FQ_OFF) { W = Wv; KS2 = 12; f = idx - FV_OFF; }
    else if (idx < FO_OFF) { W = Wq; KS2 = 6;  f = idx - FQ_OFF; }
    else                   { W = Wo; KS2 = 6;  f = idx - FO_OFF; }
    const int lane = f & 31;
    const int kk   = (f >> 5) % KS2;
    const int nt   = (f >> 5) / KS2;
    const int col  = nt * 8 + (lane >> 2);
    const int kb   = kk * 16 + (lane & 3);
    uint4 v;
    v.x = __float_as_uint(to_tf32(W[(kb     ) * 96 + col]));
    v.y = __float_as_uint(to_tf32(W[(kb +  4) * 96 + col]));
    v.z = __float_as_uint(to_tf32(W[(kb +  8) * 96 + col]));
    v.w = __float_as_uint(to_tf32(W[(kb + 12) * 96 + col]));
    gWF[idx] = v;
}

// m32 x n(8*NT) warp tile; A via ldsm, B via LDG.128 fragments (dbl-buffered).
template <int NT, int KS2, int LDA, bool TRANS, bool CVT, int LDOUT>
__device__ __forceinline__ void gemm_m32(const float* __restrict__ sA,
                                         const uint4* __restrict__ Wf,
                                         const float* __restrict__ bias,
                                         float* __restrict__ sOut,
                                         float scale, int m0, int ntb, int lane) {
    const int g = lane >> 2, tig = lane & 3;
    const uint32_t aBase  = smem_u32(sA) + (a_lane_off(m0, LDA, lane) << 2);
    const uint32_t aBase2 = aBase + 16 * LDA * 4;
    const uint4* wbase = Wf + (ntb * KS2) * 32 + lane;

    float acc[2][NT][4];
#pragma unroll
    for (int mt = 0; mt < 2; mt++)
#pragma unroll
        for (int j = 0; j < NT; j++)
#pragma unroll
            for (int x = 0; x < 4; x++) acc[mt][j][x] = 0.f;

    uint4 B[2][NT];
#pragma unroll
    for (int j = 0; j < NT; j++) B[0][j] = wbase[j * (KS2 * 32)];

#pragma unroll
    for (int kk = 0; kk < KS2; kk++) {
        const int cur = kk & 1, nxt = cur ^ 1;
        uint32_t A0[4], A1[4], A2[4], A3[4];
        ldsm4(A0, aBase  + kk * 64);
        ldsm4(A1, aBase  + kk * 64 + 32);
        ldsm4(A2, aBase2 + kk * 64);
        ldsm4(A3, aBase2 + kk * 64 + 32);
        if (kk + 1 < KS2) {
#pragma unroll
            for (int j = 0; j < NT; j++)
                B[nxt][j] = wbase[j * (KS2 * 32) + (kk + 1) * 32];
        }
#pragma unroll
        for (int j = 0; j < NT; j++) {
            mma8(acc[0][j], A0, B[cur][j].x, B[cur][j].y);
            mma8(acc[0][j], A1, B[cur][j].z, B[cur][j].w);
            mma8(acc[1][j], A2, B[cur][j].x, B[cur][j].y);
            mma8(acc[1][j], A3, B[cur][j].z, B[cur][j].w);
        }
    }
#pragma unroll
    for (int mt = 0; mt < 2; mt++)
#pragma unroll
        for (int j = 0; j < NT; j++) {
            const int col = (ntb + j) * 8 + 2 * tig;
            const float b0 = bias[col], b1 = bias[col + 1];
#pragma unroll
            for (int half = 0; half < 2; half++) {
                const int r = m0 + mt * 16 + g + half * 8;
                float v0 = (acc[mt][j][half * 2 + 0] + b0) * scale;
                float v1 = (acc[mt][j][half * 2 + 1] + b1) * scale;
                if (CVT) { v0 = to_tf32(v0); v1 = to_tf32(v1); }
                if (TRANS) {
                    sOut[col * LDOUT + r]       = v0;
                    sOut[(col + 1) * LDOUT + r] = v1;
                } else {
                    *reinterpret_cast<float2*>(&sOut[r * LDOUT + col]) = make_float2(v0, v1);
                }
            }
        }
}

// m16 x n(8*NT) warp tile (O-projection over 16 warps).
template <int NT, int KS2, int LDA, bool TRANS, int LDOUT>
__device__ __forceinline__ void gemm_m16(const float* __restrict__ sA,
                                         const uint4* __restrict__ Wf,
                                         const float* __restrict__ bias,
                                         float* __restrict__ sOut,
                                         int m0, int ntb, int lane) {
    const int g = lane >> 2, tig = lane & 3;
    const uint32_t aBase = smem_u32(sA) + (a_lane_off(m0, LDA, lane) << 2);
    const uint4* wbase = Wf + (ntb * KS2) * 32 + lane;

    float acc[NT][4];
#pragma unroll
    for (int j = 0; j < NT; j++)
#pragma unroll
        for (int x = 0; x < 4; x++) acc[j][x] = 0.f;

    uint4 B[2][NT];
#pragma unroll
    for (int j = 0; j < NT; j++) B[0][j] = wbase[j * (KS2 * 32)];

#pragma unroll
    for (int kk = 0; kk < KS2; kk++) {
        const int cur = kk & 1, nxt = cur ^ 1;
        uint32_t A0[4], A1[4];
        ldsm4(A0, aBase + kk * 64);
        ldsm4(A1, aBase + kk * 64 + 32);
        if (kk + 1 < KS2) {
#pragma unroll
            for (int j = 0; j < NT; j++)
                B[nxt][j] = wbase[j * (KS2 * 32) + (kk + 1) * 32];
        }
#pragma unroll
        for (int j = 0; j < NT; j++) {
            mma8(acc[j], A0, B[cur][j].x, B[cur][j].y);
            mma8(acc[j], A1, B[cur][j].z, B[cur][j].w);
        }
    }
#pragma unroll
    for (int j = 0; j < NT; j++) {
        const int col = (ntb + j) * 8 + 2 * tig;
        const float b0 = bias[col], b1 = bias[col + 1];
#pragma unroll
        for (int half = 0; half < 2; half++) {
            const int r = m0 + g + half * 8;
            const float v0 = acc[j][half * 2 + 0] + b0;
            const float v1 = acc[j][half * 2 + 1] + b1;
            if (TRANS) {
                sOut[col * LDOUT + r]       = v0;
                sOut[(col + 1) * LDOUT + r] = v1;
            } else {
                *reinterpret_cast<float2*>(&sOut[r * LDOUT + col]) = make_float2(v0, v1);
            }
        }
    }
}

// conflict-free staging: lane -> (4 channels x 8 tokens)
template <int LD>
__device__ __forceinline__ void stage_X(const float* __restrict__ img,
                                        float* __restrict__ sX,
                                        int ch, int h0, int w0, int warp, int lane) {
    const int u = lane & 7;
    const int v = lane >> 3;
    for (int it = warp; it < ch * 2; it += 16) {
        const int cg = it >> 3, tg = it & 7;
        const int c = cg * 4 + v;
        const float val = img[(size_t)c * (IMG * IMG) + (size_t)(h0 + tg) * IMG + w0 + u];
        sX[(tg * 8 + u) * LD + c] = to_tf32(val);
    }
}

__global__ void __launch_bounds__(THREADS, 1)
xswa_kernel(const float* __restrict__ xq, const float* __restrict__ xkv,
            const float* __restrict__ bq, const float* __restrict__ bk,
            const float* __restrict__ bv, const float* __restrict__ bias_table,
            const float* __restrict__ bo, float* __restrict__ out) {
    extern __shared__ float sm[];
    const int tid  = threadIdx.x;
    const int warp = tid >> 5;
    const int lane = tid & 31;
    const int g = lane >> 2, tig = lane & 3;

    const int win = blockIdx.x;
    const int b   = win >> 10;
    const int rem = win & 1023;
    const int h0  = (rem >> 5) << 3;
    const int w0  = (rem & 31) << 3;

    const float* xq_b  = xq  + (size_t)b * CQ  * (IMG * IMG);
    const float* xkv_b = xkv + (size_t)b * CKV * (IMG * IMG);

    // ---- stage inputs + tables ----
    for (int i = tid; i < 225 * NH; i += THREADS) sm[OFF_BT + i] = bias_table[i];
    if (tid < 96) {
        sm[OFF_BQ + tid] = bq[tid];
        sm[OFF_BK + tid] = bk[tid];
        sm[OFF_BV + tid] = bv[tid];
        sm[OFF_BO + tid] = bo[tid];
    }
    stage_X<LD_X>(xkv_b, sm + OFF_XKV, CKV, h0, w0, warp, lane);
    stage_X<LD_XQ>(xq_b, sm + OFF_XQ, CQ, h0, w0, warp, lane);
    __syncthreads();

    // ---- projections, one phase: w0-5 K, w6-11 V, w12-15 Q ----
    if (warp < 6) {
        gemm_m32<4, 12, LD_X, false, true, LD_QK>(
            sm + OFF_XKV, gWF + FK_OFF, sm + OFF_BK, sm + OFF_K, 1.f,
            (warp & 1) * 32, (warp >> 1) * 4, lane);
    } else if (warp < 12) {
        const int w = warp - 6;
        gemm_m32<4, 12, LD_X, true, true, LD_VT>(
            sm + OFF_XKV, gWF + FV_OFF, sm + OFF_BV, sm + OFF_VT, 1.f,
            (w & 1) * 32, (w >> 1) * 4, lane);
    } else {
        const int w = warp - 12;
        gemm_m32<6, 6, LD_XQ, false, true, LD_QK>(
            sm + OFF_XQ, gWF + FQ_OFF, sm + OFF_BQ, sm + OFF_Q, 0.25f,
            (w & 1) * 32, (w >> 1) * 6, lane);
    }
    __syncthreads();

    // ---- attention, register-resident P: 12 warps = (head, m32) ----
    if (warp < 12) {
        const int head = warp >> 1;
        const int m0   = (warp & 1) * 32;

        // scores: m32 x n64, k16
        float acc[2][8][4];
        {
            const uint32_t aAddr = smem_u32(sm + OFF_Q)
                + ((a_lane_off(m0, LD_QK, lane) + head * 16) << 2);
            uint32_t A0[4], A1[4], A2[4], A3[4];
            ldsm4(A0, aAddr);
            ldsm4(A1, aAddr + 32);
            ldsm4(A2, aAddr + 16 * LD_QK * 4);
            ldsm4(A3, aAddr + 16 * LD_QK * 4 + 32);
#pragma unroll
            for (int mt = 0; mt < 2; mt++)
#pragma unroll
                for (int nt = 0; nt < 8; nt++)
#pragma unroll
                    for (int x = 0; x < 4; x++) acc[mt][nt][x] = 0.f;
#pragma unroll
            for (int nt = 0; nt < 8; nt++) {
                uint32_t Bf[4];
                ldsm4(Bf, smem_u32(sm + OFF_K)
                    + ((b_lane_off(nt * 8, LD_QK, lane) + head * 16) << 2));
                mma8(acc[0][nt], A0, Bf[0], Bf[1]);
                mma8(acc[0][nt], A1, Bf[2], Bf[3]);
                mma8(acc[1][nt], A2, Bf[0], Bf[1]);
                mma8(acc[1][nt], A3, Bf[2], Bf[3]);
            }
        }

        // softmax in registers: exp(score + bias), row sums over quad
        float rs[4] = {0.f, 0.f, 0.f, 0.f};
        const float* bt = sm + OFF_BT;
#pragma unroll
        for (int mt = 0; mt < 2; mt++) {
            const int i0 = m0 + mt * 16 + g, i1 = i0 + 8;
            const int ih0 = i0 >> 3, iw0 = i0 & 7;
            const int ih1 = i1 >> 3, iw1 = i1 & 7;
#pragma unroll
            for (int nt = 0; nt < 8; nt++) {
                const int j0 = nt * 8 + 2 * tig;
                const int jh0 = j0 >> 3, jw0 = j0 & 7;
                const int jh1 = (j0 + 1) >> 3, jw1 = (j0 + 1) & 7;
                acc[mt][nt][0] = __expf(acc[mt][nt][0] + bt[((ih0 - jh0 + 7) * 15 + (iw0 - jw0 + 7)) * NH + head]);
                acc[mt][nt][1] = __expf(acc[mt][nt][1] + bt[((ih0 - jh1 + 7) * 15 + (iw0 - jw1 + 7)) * NH + head]);
                acc[mt][nt][2] = __expf(acc[mt][nt][2] + bt[((ih1 - jh0 + 7) * 15 + (iw1 - jw0 + 7)) * NH + head]);
                acc[mt][nt][3] = __expf(acc[mt][nt][3] + bt[((ih1 - jh1 + 7) * 15 + (iw1 - jw1 + 7)) * NH + head]);
                rs[mt * 2]     += acc[mt][nt][0] + acc[mt][nt][1];
                rs[mt * 2 + 1] += acc[mt][nt][2] + acc[mt][nt][3];
            }
        }
#pragma unroll
        for (int q = 0; q < 4; q++) {
            rs[q] += __shfl_xor_sync(0xffffffffu, rs[q], 1);
            rs[q] += __shfl_xor_sync(0xffffffffu, rs[q], 2);
            rs[q] = 1.f / rs[q];
        }

        // AV: convert C-frags -> A-frags per k16 chunk, mma against V^T
        float av[2][2][4];
#pragma unroll
        for (int mt = 0; mt < 2; mt++)
#pragma unroll
            for (int j = 0; j < 2; j++)
#pragma unroll
                for (int x = 0; x < 4; x++) av[mt][j][x] = 0.f;

        const uint32_t bB0 = smem_u32(sm + OFF_VT) + (b_lane_off(head * 16,     LD_VT, lane) << 2);
        const uint32_t bB1 = smem_u32(sm + OFF_VT) + (b_lane_off(head * 16 + 8, LD_VT, lane) << 2);
#pragma unroll
        for (int kk2 = 0; kk2 < 4; kk2++) {
            uint32_t B0[4], B1[4];
            ldsm4(B0, bB0 + kk2 * 64);
            ldsm4(B1, bB1 + kk2 * 64);
#pragma unroll
            for (int mt = 0; mt < 2; mt++) {
                uint32_t afL[4], afH[4];
                cfrag_to_afrag(acc[mt][2 * kk2],     afL, lane);
                cfrag_to_afrag(acc[mt][2 * kk2 + 1], afH, lane);
                mma8(av[mt][0], afL, B0[0], B0[1]);
                mma8(av[mt][0], afH, B0[2], B0[3]);
                mma8(av[mt][1], afL, B1[0], B1[1]);
                mma8(av[mt][1], afH, B1[2], B1[3]);
            }
        }

        // normalize + write O
        float* sO = sm + OFF_O;
#pragma unroll
        for (int mt = 0; mt < 2; mt++) {
            const float inv0 = rs[mt * 2], inv1 = rs[mt * 2 + 1];
#pragma unroll
            for (int j = 0; j < 2; j++) {
                const int col = head * 16 + j * 8 + 2 * tig;
                *reinterpret_cast<float2*>(&sO[(m0 + mt * 16 + g) * LD_O + col]) =
                    make_float2(to_tf32(av[mt][j][0] * inv0), to_tf32(av[mt][j][1] * inv0));
                *reinterpret_cast<float2*>(&sO[(m0 + mt * 16 + g + 8) * LD_O + col]) =
                    make_float2(to_tf32(av[mt][j][2] * inv1), to_tf32(av[mt][j][3] * inv1));
            }
        }
    }
    __syncthreads();

    // ---- output projection: 16 warps m16n24, O @ Wo + bo -> F [96][64] ----
    gemm_m16<3, 6, LD_O, true, LD_F>(
        sm + OFF_O, gWF + FO_OFF, sm + OFF_BO, sm + OFF_F,
        (warp & 3) * 16, (warp >> 2) * 3, lane);
    __syncthreads();

    // ---- coalesced store ----
    {
        const float* sF = sm + OFF_F;
        float* out_b = out + (size_t)b * CQ * (IMG * IMG);
#pragma unroll
        for (int idx = tid; idx < CQ * WIN / 2; idx += THREADS) {
            const int c  = idx >> 5;
            const int t0 = (idx & 31) * 2;
            const float2 v = *reinterpret_cast<const float2*>(&sF[c * LD_F + t0]);
            float* dst = out_b + (size_t)c * (IMG * IMG)
                       + (size_t)(h0 + (t0 >> 3)) * IMG + (w0 + (t0 & 7));
            *reinterpret_cast<float2*>(dst) = v;
        }
    }
}

} // namespace

extern "C" void kernel_launch(void* const* d_in, const int* in_sizes, int n_in,
                              void* d_out, int out_size) {
    const float* xq   = (const float*)d_in[0];
    const float* xkv  = (const float*)d_in[1];
    const float* Wq   = (const float*)d_in[2];
    const float* bq   = (const float*)d_in[3];
    const float* Wk   = (const float*)d_in[4];
    const float* bk   = (const float*)d_in[5];
    const float* Wv   = (const float*)d_in[6];
    const float* bv   = (const float*)d_in[7];
    const float* bias_table = (const float*)d_in[8];
    const float* Wo   = (const float*)d_in[9];
    const float* bo   = (const float*)d_in[10];
    float* out = (float*)d_out;

    const int B = in_sizes[0] / (CQ * IMG * IMG);
    const int nwin = B * (IMG / 8) * (IMG / 8);

    prep_kernel<<<(F_TOTAL + 255) / 256, 256>>>(Wk, Wv, Wq, Wo);

    const int smem_bytes = SMEM_FLOATS * (int)sizeof(float);
    cudaFuncSetAttribute(xswa_kernel, cudaFuncAttributeMaxDynamicSharedMemorySize, smem_bytes);
    xswa_kernel<<<nwin, THREADS, smem_bytes>>>(xq, xkv, bq, bk, bv,
                                               bias_table, bo, out);
}

// round 10
// speedup vs baseline: 1.2163x; 1.2163x over previous
#include <cuda_runtime.h>
#include <cuda_fp16.h>
#include <cstdint>

// CrossSpatialWindowAttention — fused fp16 mma (m16n8k16, fp32 accum), pre-swizzled
// weight fragments (LDG.128, L1-resident), register-resident P with shuffle-free
// C->A fragment conversion. 512 threads, ~86KB smem, 1 CTA/window.

namespace {

constexpr int IMG     = 256;
constexpr int CQ      = 96;
constexpr int CKV     = 192;
constexpr int NH      = 6;
constexpr int WIN     = 64;
constexpr int THREADS = 512;

// weight-fragment table (uint4 = 2 k16-steps of a b16 B-fragment): [nt][k32][lane]
constexpr int FK_OFF = 0;      // Wk: 12 nt * 6 k32 * 32
constexpr int FV_OFF = 2304;   // Wv
constexpr int FQ_OFF = 4608;   // Wq: 12 nt * 3 k32 * 32
constexpr int FO_OFF = 5760;   // Wo
constexpr int F_TOTAL = 6912;
__device__ uint4 gWF[F_TOTAL];

// leading dims in HALVES: (LDH/8) odd -> conflict-free ldmatrix
constexpr int LDH_X  = 200;   // XKV [64 tok][192 ch]
constexpr int LDH_QK = 104;   // XQ/Q/K/O [64 tok][96 ch]
constexpr int LDH_VT = 72;    // VT [96 ch][64 tok]
constexpr int LD_F   = 68;    // F fp32 [96 ch][64 tok]

// smem BYTE offsets
constexpr int OFF_XKV = 0;        // 25600
constexpr int OFF_XQ  = 25600;    // 13312 (later: attn-out O)
constexpr int OFF_Q   = 38912;    // 13312 (later: F fp32, spans Q+K 26624 >= 26112)
constexpr int OFF_K   = 52224;    // 13312
constexpr int OFF_VT  = 65536;    // 13824
constexpr int OFF_BT  = 79360;    // 5400 (fp32)
constexpr int OFF_BQ  = 84760;    // 384
constexpr int OFF_BK  = 85144;
constexpr int OFF_BV  = 85528;
constexpr int OFF_BO  = 85912;
constexpr int SMEM_BYTES = 86400;
constexpr int OFF_O = OFF_XQ;
constexpr int OFF_F = OFF_Q;

__device__ __forceinline__ uint32_t smem_u32(const void* p) {
    return (uint32_t)__cvta_generic_to_shared(p);
}

__device__ __forceinline__ void ldsm4(uint32_t r[4], uint32_t addr) {
    asm volatile("ldmatrix.sync.aligned.m8n8.x4.shared.b16 {%0,%1,%2,%3}, [%4];"
                 : "=r"(r[0]), "=r"(r[1]), "=r"(r[2]), "=r"(r[3]) : "r"(addr));
}

__device__ __forceinline__ void mma16(float c[4], const uint32_t a[4],
                                      uint32_t b0, uint32_t b1) {
    asm volatile("mma.sync.aligned.m16n8k16.row.col.f32.f16.f16.f32 "
                 "{%0,%1,%2,%3},{%4,%5,%6,%7},{%8,%9},{%0,%1,%2,%3};"
                 : "+f"(c[0]), "+f"(c[1]), "+f"(c[2]), "+f"(c[3])
                 : "r"(a[0]), "r"(a[1]), "r"(a[2]), "r"(a[3]), "r"(b0), "r"(b1));
}

__device__ __forceinline__ uint32_t pack2(float a, float b) {
    __half2 h = __floats2half2_rn(a, b);
    return *reinterpret_cast<uint32_t*>(&h);
}

// A-fragment ldmatrix byte offset (m16k16 tile at row m0), row-major halves, ld LDH
__device__ __forceinline__ uint32_t a_off16(int m0, int ldh, int lane) {
    const int row = m0 + (lane & 7) + ((lane >> 3) & 1) * 8;
    return (uint32_t)(row * ldh * 2 + ((lane >> 4) & 1) * 16);
}
// B-fragment ldmatrix byte offset (n16 x k16 at n0), n-major halves
__device__ __forceinline__ uint32_t b_off16(int n0, int ldh, int lane) {
    const int row = n0 + (lane & 7) + ((lane >> 4) & 1) * 8;
    return (uint32_t)(row * ldh * 2 + ((lane >> 3) & 1) * 16);
}

// ---- prep: pack weights into fp16 B-fragment order ----
// uint4 = {b0(k16a), b1(k16a), b0(k16b), b1(k16b)}, col = nt*8 + g, k in pairs
__global__ void prep_kernel(const float* __restrict__ Wk, const float* __restrict__ Wv,
                            const float* __restrict__ Wq, const float* __restrict__ Wo) {
    const int idx = blockIdx.x * blockDim.x + threadIdx.x;
    if (idx >= F_TOTAL) return;
    const float* W; int K32, f;
    if (idx < FV_OFF)      { W = Wk; K32 = 6; f = idx; }
    else if (idx < FQ_OFF) { W = Wv; K32 = 6; f = idx - FV_OFF; }
    else if (idx < FO_OFF) { W = Wq; K32 = 3; f = idx - FQ_OFF; }
    else                   { W = Wo; K32 = 3; f = idx - FO_OFF; }
    const int lane = f & 31;
    const int kk   = (f >> 5) % K32;
    const int nt   = (f >> 5) / K32;
    const int g = lane >> 2, tig = lane & 3;
    const int col = nt * 8 + g;
    const int kb  = kk * 32;
    uint4 v;
    v.x = pack2(W[(kb +      2*tig) * 96 + col], W[(kb +      2*tig + 1) * 96 + col]);
    v.y = pack2(W[(kb +  8 + 2*tig) * 96 + col], W[(kb +  8 + 2*tig + 1) * 96 + col]);
    v.z = pack2(W[(kb + 16 + 2*tig) * 96 + col], W[(kb + 16 + 2*tig + 1) * 96 + col]);
    v.w = pack2(W[(kb + 24 + 2*tig) * 96 + col], W[(kb + 24 + 2*tig + 1) * 96 + col]);
    gWF[idx] = v;
}

// GEMM: OUT = A[64][32*K32] @ W. MT m16-tiles, NT n8-tiles, A fp16 smem (ldsm),
// B fragments via LDG.128 (double-buffered if PREF). MODE 0: half2 row-major,
// 1: half transposed, 2: f32 transposed.
template <int MT, int NT, int K32, int LDAH, int MODE, int LDOUT, bool PREF>
__device__ __forceinline__ void gemm_h(const __half* sA, const uint4* __restrict__ Wf,
                                       const float* __restrict__ bias, void* sOut,
                                       float scale, int m0, int ntb, int lane) {
    const int g = lane >> 2, tig = lane & 3;
    const uint32_t aAddr0 = smem_u32(sA) + a_off16(m0, LDAH, lane);
    const uint32_t aAddr1 = aAddr0 + 16 * LDAH * 2;
    const uint4* wbase = Wf + lane;

    float acc[MT][NT][4];
#pragma unroll
    for (int mt = 0; mt < MT; mt++)
#pragma unroll
        for (int j = 0; j < NT; j++)
#pragma unroll
            for (int x = 0; x < 4; x++) acc[mt][j][x] = 0.f;

    uint4 B[2][NT];
    if (PREF) {
#pragma unroll
        for (int j = 0; j < NT; j++) B[0][j] = wbase[((ntb + j) * K32) * 32];
    }

#pragma unroll
    for (int s = 0; s < K32; s++) {
        const int cur = PREF ? (s & 1) : 0;
        if (!PREF) {
#pragma unroll
            for (int j = 0; j < NT; j++) B[0][j] = wbase[((ntb + j) * K32 + s) * 32];
        }
        uint32_t Af[2][2][4];
        ldsm4(Af[0][0], aAddr0 + s * 64);
        ldsm4(Af[0][1], aAddr0 + s * 64 + 32);
        if (MT == 2) {
            ldsm4(Af[1][0], aAddr1 + s * 64);
            ldsm4(Af[1][1], aAddr1 + s * 64 + 32);
        }
        if (PREF && s + 1 < K32) {
#pragma unroll
            for (int j = 0; j < NT; j++)
                B[cur ^ 1][j] = wbase[((ntb + j) * K32 + s + 1) * 32];
        }
#pragma unroll
        for (int j = 0; j < NT; j++)
#pragma unroll
            for (int mt = 0; mt < MT; mt++) {
                mma16(acc[mt][j], Af[mt][0], B[cur][j].x, B[cur][j].y);
                mma16(acc[mt][j], Af[mt][1], B[cur][j].z, B[cur][j].w);
            }
    }
#pragma unroll
    for (int mt = 0; mt < MT; mt++)
#pragma unroll
        for (int j = 0; j < NT; j++) {
            const int col = (ntb + j) * 8 + 2 * tig;
            const float b0 = bias[col], b1 = bias[col + 1];
#pragma unroll
            for (int h = 0; h < 2; h++) {
                const int r = m0 + mt * 16 + g + h * 8;
                const float v0 = (acc[mt][j][2 * h + 0] + b0) * scale;
                const float v1 = (acc[mt][j][2 * h + 1] + b1) * scale;
                if (MODE == 0) {
                    __half2 hv = __floats2half2_rn(v0, v1);
                    *reinterpret_cast<__half2*>((__half*)sOut + r * LDOUT + col) = hv;
                } else if (MODE == 1) {
                    ((__half*)sOut)[col * LDOUT + r]       = __float2half_rn(v0);
                    ((__half*)sOut)[(col + 1) * LDOUT + r] = __float2half_rn(v1);
                } else {
                    ((float*)sOut)[col * LDOUT + r]       = v0;
                    ((float*)sOut)[(col + 1) * LDOUT + r] = v1;
                }
            }
        }
}

// conflict-free staging to token-major fp16: lane -> (4 channels x 8 tokens)
template <int LDH>
__device__ __forceinline__ void stage_Xh(const float* __restrict__ img,
                                         __half* __restrict__ sX,
                                         int ch, int h0, int w0, int warp, int lane) {
    const int u = lane & 7;
    const int v = lane >> 3;
    for (int it = warp; it < ch * 2; it += 16) {
        const int cg = it >> 3, tg = it & 7;
        const int c = cg * 4 + v;
        const float val = img[(size_t)c * (IMG * IMG) + (size_t)(h0 + tg) * IMG + w0 + u];
        sX[(tg * 8 + u) * LDH + c] = __float2half_rn(val);
    }
}

__global__ void __launch_bounds__(THREADS, 1)
xswa_kernel(const float* __restrict__ xq, const float* __restrict__ xkv,
            const float* __restrict__ bq, const float* __restrict__ bk,
            const float* __restrict__ bv, const float* __restrict__ bias_table,
            const float* __restrict__ bo, float* __restrict__ out) {
    extern __shared__ char smc[];
    __half* sXKV = reinterpret_cast<__half*>(smc + OFF_XKV);
    __half* sXQ  = reinterpret_cast<__half*>(smc + OFF_XQ);
    __half* sQ   = reinterpret_cast<__half*>(smc + OFF_Q);
    __half* sK   = reinterpret_cast<__half*>(smc + OFF_K);
    __half* sVT  = reinterpret_cast<__half*>(smc + OFF_VT);
    __half* sO   = reinterpret_cast<__half*>(smc + OFF_O);
    float*  sF   = reinterpret_cast<float*>(smc + OFF_F);
    float*  sBT  = reinterpret_cast<float*>(smc + OFF_BT);
    float*  sBQ  = reinterpret_cast<float*>(smc + OFF_BQ);
    float*  sBK  = reinterpret_cast<float*>(smc + OFF_BK);
    float*  sBV  = reinterpret_cast<float*>(smc + OFF_BV);
    float*  sBO  = reinterpret_cast<float*>(smc + OFF_BO);

    const int tid  = threadIdx.x;
    const int warp = tid >> 5;
    const int lane = tid & 31;
    const int g = lane >> 2, tig = lane & 3;

    const int win = blockIdx.x;
    const int b   = win >> 10;
    const int rem = win & 1023;
    const int h0  = (rem >> 5) << 3;
    const int w0  = (rem & 31) << 3;

    const float* xq_b  = xq  + (size_t)b * CQ  * (IMG * IMG);
    const float* xkv_b = xkv + (size_t)b * CKV * (IMG * IMG);

    // ---- stage inputs + tables ----
    for (int i = tid; i < 225 * NH; i += THREADS) sBT[i] = bias_table[i];
    if (tid < 96) {
        sBQ[tid] = bq[tid];
        sBK[tid] = bk[tid];
        sBV[tid] = bv[tid];
        sBO[tid] = bo[tid];
    }
    stage_Xh<LDH_X>(xkv_b, sXKV, CKV, h0, w0, warp, lane);
    stage_Xh<LDH_QK>(xq_b, sXQ, CQ, h0, w0, warp, lane);
    __syncthreads();

    // ---- projections, one phase: w0-5 K, w6-11 V(->VT), w12-15 Q ----
    if (warp < 6) {
        gemm_h<2, 4, 6, LDH_X, 0, LDH_QK, true>(
            sXKV, gWF + FK_OFF, sBK, sK, 1.f, (warp & 1) * 32, (warp >> 1) * 4, lane);
    } else if (warp < 12) {
        const int w = warp - 6;
        gemm_h<2, 4, 6, LDH_X, 1, LDH_VT, true>(
            sXKV, gWF + FV_OFF, sBV, sVT, 1.f, (w & 1) * 32, (w >> 1) * 4, lane);
    } else {
        const int w = warp - 12;
        gemm_h<2, 6, 3, LDH_QK, 0, LDH_QK, false>(
            sXQ, gWF + FQ_OFF, sBQ, sQ, 0.25f, (w & 1) * 32, (w >> 1) * 6, lane);
    }
    __syncthreads();

    // ---- attention, register-resident P: 12 warps = (head, m32) ----
    if (warp < 12) {
        const int head = warp >> 1;
        const int m0   = (warp & 1) * 32;

        // scores: m32 x n64, k16 (one fp16 k-step)
        float acc[2][8][4];
        {
            const uint32_t qa = smem_u32(sQ) + a_off16(m0, LDH_QK, lane) + head * 32;
            uint32_t Af[2][4];
            ldsm4(Af[0], qa);
            ldsm4(Af[1], qa + 16 * LDH_QK * 2);
#pragma unroll
            for (int mt = 0; mt < 2; mt++)
#pragma unroll
                for (int nt = 0; nt < 8; nt++)
#pragma unroll
                    for (int x = 0; x < 4; x++) acc[mt][nt][x] = 0.f;
#pragma unroll
            for (int jn = 0; jn < 4; jn++) {
                uint32_t Bf[4];
                ldsm4(Bf, smem_u32(sK) + b_off16(jn * 16, LDH_QK, lane) + head * 32);
#pragma unroll
                for (int mt = 0; mt < 2; mt++) {
                    mma16(acc[mt][2 * jn],     Af[mt], Bf[0], Bf[1]);
                    mma16(acc[mt][2 * jn + 1], Af[mt], Bf[2], Bf[3]);
                }
            }
        }

        // softmax in registers: exp(score + bias), row sums over quad
        float rs[4] = {0.f, 0.f, 0.f, 0.f};
#pragma unroll
        for (int mt = 0; mt < 2; mt++) {
            const int i0 = m0 + mt * 16 + g, i1 = i0 + 8;
            const int ih0 = i0 >> 3, iw0 = i0 & 7;
            const int ih1 = i1 >> 3, iw1 = i1 & 7;
#pragma unroll
            for (int nt = 0; nt < 8; nt++) {
                const int j0 = nt * 8 + 2 * tig;
                const int jh0 = j0 >> 3, jw0 = j0 & 7;
                const int jh1 = (j0 + 1) >> 3, jw1 = (j0 + 1) & 7;
                acc[mt][nt][0] = __expf(acc[mt][nt][0] + sBT[((ih0 - jh0 + 7) * 15 + (iw0 - jw0 + 7)) * NH + head]);
                acc[mt][nt][1] = __expf(acc[mt][nt][1] + sBT[((ih0 - jh1 + 7) * 15 + (iw0 - jw1 + 7)) * NH + head]);
                acc[mt][nt][2] = __expf(acc[mt][nt][2] + sBT[((ih1 - jh0 + 7) * 15 + (iw1 - jw0 + 7)) * NH + head]);
                acc[mt][nt][3] = __expf(acc[mt][nt][3] + sBT[((ih1 - jh1 + 7) * 15 + (iw1 - jw1 + 7)) * NH + head]);
                rs[mt * 2]     += acc[mt][nt][0] + acc[mt][nt][1];
                rs[mt * 2 + 1] += acc[mt][nt][2] + acc[mt][nt][3];
            }
        }
#pragma unroll
        for (int q = 0; q < 4; q++) {
            rs[q] += __shfl_xor_sync(0xffffffffu, rs[q], 1);
            rs[q] += __shfl_xor_sync(0xffffffffu, rs[q], 2);
            rs[q] = 1.f / rs[q];
        }

        // AV: k64 in 4 k16 chunks; A-frags = packed exp'd C regs (no shuffles)
        float av[2][2][4];
#pragma unroll
        for (int mt = 0; mt < 2; mt++)
#pragma unroll
            for (int j = 0; j < 2; j++)
#pragma unroll
                for (int x = 0; x < 4; x++) av[mt][j][x] = 0.f;

        const uint32_t vb = smem_u32(sVT) + b_off16(head * 16, LDH_VT, lane);
#pragma unroll
        for (int j = 0; j < 4; j++) {
            uint32_t Bf[4];
            ldsm4(Bf, vb + j * 32);
#pragma unroll
            for (int mt = 0; mt < 2; mt++) {
                uint32_t af[4];
                af[0] = pack2(acc[mt][2 * j][0],     acc[mt][2 * j][1]);
                af[1] = pack2(acc[mt][2 * j][2],     acc[mt][2 * j][3]);
                af[2] = pack2(acc[mt][2 * j + 1][0], acc[mt][2 * j + 1][1]);
                af[3] = pack2(acc[mt][2 * j + 1][2], acc[mt][2 * j + 1][3]);
                mma16(av[mt][0], af, Bf[0], Bf[1]);
                mma16(av[mt][1], af, Bf[2], Bf[3]);
            }
        }

        // normalize + write O (fp16, token-major)
#pragma unroll
        for (int mt = 0; mt < 2; mt++) {
            const float inv0 = rs[mt * 2], inv1 = rs[mt * 2 + 1];
#pragma unroll
            for (int j = 0; j < 2; j++) {
                const int col = head * 16 + j * 8 + 2 * tig;
                const int r0 = m0 + mt * 16 + g;
                *reinterpret_cast<__half2*>(sO + r0 * LDH_QK + col) =
                    __floats2half2_rn(av[mt][j][0] * inv0, av[mt][j][1] * inv0);
                *reinterpret_cast<__half2*>(sO + (r0 + 8) * LDH_QK + col) =
                    __floats2half2_rn(av[mt][j][2] * inv1, av[mt][j][3] * inv1);
            }
        }
    }
    __syncthreads();

    // ---- output projection: 16 warps m16n24, O @ Wo + bo -> F fp32 [96][64] ----
    gemm_h<1, 3, 3, LDH_QK, 2, LD_F, true>(
        sO, gWF + FO_OFF, sBO, sF, 1.f, (warp & 3) * 16, (warp >> 2) * 3, lane);
    __syncthreads();

    // ---- coalesced store ----
    {
        float* out_b = out + (size_t)b * CQ * (IMG * IMG);
#pragma unroll
        for (int idx = tid; idx < CQ * WIN / 2; idx += THREADS) {
            const int c  = idx >> 5;
            const int t0 = (idx & 31) * 2;
            const float2 v = *reinterpret_cast<const float2*>(&sF[c * LD_F + t0]);
            float* dst = out_b + (size_t)c * (IMG * IMG)
                       + (size_t)(h0 + (t0 >> 3)) * IMG + (w0 + (t0 & 7));
            *reinterpret_cast<float2*>(dst) = v;
        }
    }
}

} // namespace

extern "C" void kernel_launch(void* const* d_in, const int* in_sizes, int n_in,
                              void* d_out, int out_size) {
    const float* xq   = (const float*)d_in[0];
    const float* xkv  = (const float*)d_in[1];
    const float* Wq   = (const float*)d_in[2];
    const float* bq   = (const float*)d_in[3];
    const float* Wk   = (const float*)d_in[4];
    const float* bk   = (const float*)d_in[5];
    const float* Wv   = (const float*)d_in[6];
    const float* bv   = (const float*)d_in[7];
    const float* bias_table = (const float*)d_in[8];
    const float* Wo   = (const float*)d_in[9];
    const float* bo   = (const float*)d_in[10];
    float* out = (float*)d_out;

    const int B = in_sizes[0] / (CQ * IMG * IMG);
    const int nwin = B * (IMG / 8) * (IMG / 8);

    prep_kernel<<<(F_TOTAL + 255) / 256, 256>>>(Wk, Wv, Wq, Wo);

    cudaFuncSetAttribute(xswa_kernel, cudaFuncAttributeMaxDynamicSharedMemorySize, SMEM_BYTES);
    xswa_kernel<<<nwin, THREADS, SMEM_BYTES>>>(xq, xkv, bq, bk, bv,
                                               bias_table, bo, out);
}

// round 11
// speedup vs baseline: 1.7259x; 1.4190x over previous
#include <cuda_runtime.h>
#include <cuda_fp16.h>
#include <cstdint>

// CrossSpatialWindowAttention — fused fp16 mma, pre-swizzled weights,
// TWO independent windows per CTA with named-barrier decoupling.
// 512 threads (warps 0-7: window A, warps 8-15: window B), ~166KB smem.

namespace {

constexpr int IMG     = 256;
constexpr int CQ      = 96;
constexpr int CKV     = 192;
constexpr int NH      = 6;
constexpr int WIN     = 64;
constexpr int THREADS = 512;

// weight-fragment table (uint4 = 2 k16-steps of fp16 B-fragment): [nt][k32][lane]
constexpr int FK_OFF = 0;
constexpr int FV_OFF = 2304;
constexpr int FQ_OFF = 4608;
constexpr int FO_OFF = 5760;
constexpr int F_TOTAL = 6912;
__device__ uint4 gWF[F_TOTAL];

// leading dims in halves: (LDH/8) odd -> conflict-free ldmatrix
constexpr int LDH_X  = 200;
constexpr int LDH_QK = 104;
constexpr int LDH_VT = 72;
constexpr int LD_F   = 68;   // fp32

// per-window smem BYTE offsets (relative to window base)
constexpr int WOFF_XKV = 0;        // 25600
constexpr int WOFF_XQ  = 25600;    // 13312 (later: attn-out O)
constexpr int WOFF_Q   = 38912;    // 13312 (later: F fp32, spans Q+K)
constexpr int WOFF_K   = 52224;    // 13312
constexpr int WOFF_VT  = 65536;    // 13824
constexpr int WBYTES   = 79360;
// shared (CTA-wide) tables
constexpr int OFF_BT = 2 * WBYTES;        // 158720, 5400 bytes
constexpr int OFF_BQ = OFF_BT + 5400;     // 164120
constexpr int OFF_BK = OFF_BQ + 384;
constexpr int OFF_BV = OFF_BK + 384;
constexpr int OFF_BO = OFF_BV + 384;
constexpr int SMEM_BYTES = OFF_BO + 384;  // 165656 -> pad
constexpr int SMEM_ALLOC = 165664;

__device__ __forceinline__ uint32_t smem_u32(const void* p) {
    return (uint32_t)__cvta_generic_to_shared(p);
}

__device__ __forceinline__ void barw(int id) {
    asm volatile("bar.sync %0, 256;" :: "r"(id) : "memory");
}

__device__ __forceinline__ void ldsm4(uint32_t r[4], uint32_t addr) {
    asm volatile("ldmatrix.sync.aligned.m8n8.x4.shared.b16 {%0,%1,%2,%3}, [%4];"
                 : "=r"(r[0]), "=r"(r[1]), "=r"(r[2]), "=r"(r[3]) : "r"(addr));
}

__device__ __forceinline__ void mma16(float c[4], const uint32_t a[4],
                                      uint32_t b0, uint32_t b1) {
    asm volatile("mma.sync.aligned.m16n8k16.row.col.f32.f16.f16.f32 "
                 "{%0,%1,%2,%3},{%4,%5,%6,%7},{%8,%9},{%0,%1,%2,%3};"
                 : "+f"(c[0]), "+f"(c[1]), "+f"(c[2]), "+f"(c[3])
                 : "r"(a[0]), "r"(a[1]), "r"(a[2]), "r"(a[3]), "r"(b0), "r"(b1));
}

__device__ __forceinline__ uint32_t pack2(float a, float b) {
    __half2 h = __floats2half2_rn(a, b);
    return *reinterpret_cast<uint32_t*>(&h);
}

__device__ __forceinline__ uint32_t a_off16(int m0, int ldh, int lane) {
    const int row = m0 + (lane & 7) + ((lane >> 3) & 1) * 8;
    return (uint32_t)(row * ldh * 2 + ((lane >> 4) & 1) * 16);
}
__device__ __forceinline__ uint32_t b_off16(int n0, int ldh, int lane) {
    const int row = n0 + (lane & 7) + ((lane >> 4) & 1) * 8;
    return (uint32_t)(row * ldh * 2 + ((lane >> 3) & 1) * 16);
}

// ---- prep: pack weights into fp16 B-fragment order ----
__global__ void prep_kernel(const float* __restrict__ Wk, const float* __restrict__ Wv,
                            const float* __restrict__ Wq, const float* __restrict__ Wo) {
    const int idx = blockIdx.x * blockDim.x + threadIdx.x;
    if (idx >= F_TOTAL) return;
    const float* W; int K32, f;
    if (idx < FV_OFF)      { W = Wk; K32 = 6; f = idx; }
    else if (idx < FQ_OFF) { W = Wv; K32 = 6; f = idx - FV_OFF; }
    else if (idx < FO_OFF) { W = Wq; K32 = 3; f = idx - FQ_OFF; }
    else                   { W = Wo; K32 = 3; f = idx - FO_OFF; }
    const int lane = f & 31;
    const int kk   = (f >> 5) % K32;
    const int nt   = (f >> 5) / K32;
    const int g = lane >> 2, tig = lane & 3;
    const int col = nt * 8 + g;
    const int kb  = kk * 32;
    uint4 v;
    v.x = pack2(W[(kb +      2*tig) * 96 + col], W[(kb +      2*tig + 1) * 96 + col]);
    v.y = pack2(W[(kb +  8 + 2*tig) * 96 + col], W[(kb +  8 + 2*tig + 1) * 96 + col]);
    v.z = pack2(W[(kb + 16 + 2*tig) * 96 + col], W[(kb + 16 + 2*tig + 1) * 96 + col]);
    v.w = pack2(W[(kb + 24 + 2*tig) * 96 + col], W[(kb + 24 + 2*tig + 1) * 96 + col]);
    gWF[idx] = v;
}

// GEMM: MT m16-tiles, NT n8-tiles, A fp16 smem (ldsm), B frags via LDG.128
// (double-buffered if PREF). MODE 0: half2 row-major, 1: half transposed, 2: f32 transposed.
template <int MT, int NT, int K32, int LDAH, int MODE, int LDOUT, bool PREF>
__device__ __forceinline__ void gemm_h(const __half* sA, const uint4* __restrict__ Wf,
                                       const float* __restrict__ bias, void* sOut,
                                       float scale, int m0, int ntb, int lane) {
    const int g = lane >> 2, tig = lane & 3;
    const uint32_t aAddr0 = smem_u32(sA) + a_off16(m0, LDAH, lane);
    const uint32_t aAddr1 = aAddr0 + 16 * LDAH * 2;
    const uint4* wbase = Wf + lane;

    float acc[MT][NT][4];
#pragma unroll
    for (int mt = 0; mt < MT; mt++)
#pragma unroll
        for (int j = 0; j < NT; j++)
#pragma unroll
            for (int x = 0; x < 4; x++) acc[mt][j][x] = 0.f;

    uint4 B[2][NT];
    if (PREF) {
#pragma unroll
        for (int j = 0; j < NT; j++) B[0][j] = wbase[((ntb + j) * K32) * 32];
    }

#pragma unroll
    for (int s = 0; s < K32; s++) {
        const int cur = PREF ? (s & 1) : 0;
        if (!PREF) {
#pragma unroll
            for (int j = 0; j < NT; j++) B[0][j] = wbase[((ntb + j) * K32 + s) * 32];
        }
        uint32_t Af[2][2][4];
        ldsm4(Af[0][0], aAddr0 + s * 64);
        ldsm4(Af[0][1], aAddr0 + s * 64 + 32);
        if (MT == 2) {
            ldsm4(Af[1][0], aAddr1 + s * 64);
            ldsm4(Af[1][1], aAddr1 + s * 64 + 32);
        }
        if (PREF && s + 1 < K32) {
#pragma unroll
            for (int j = 0; j < NT; j++)
                B[cur ^ 1][j] = wbase[((ntb + j) * K32 + s + 1) * 32];
        }
#pragma unroll
        for (int j = 0; j < NT; j++)
#pragma unroll
            for (int mt = 0; mt < MT; mt++) {
                mma16(acc[mt][j], Af[mt][0], B[cur][j].x, B[cur][j].y);
                mma16(acc[mt][j], Af[mt][1], B[cur][j].z, B[cur][j].w);
            }
    }
#pragma unroll
    for (int mt = 0; mt < MT; mt++)
#pragma unroll
        for (int j = 0; j < NT; j++) {
            const int col = (ntb + j) * 8 + 2 * tig;
            const float b0 = bias[col], b1 = bias[col + 1];
#pragma unroll
            for (int h = 0; h < 2; h++) {
                const int r = m0 + mt * 16 + g + h * 8;
                const float v0 = (acc[mt][j][2 * h + 0] + b0) * scale;
                const float v1 = (acc[mt][j][2 * h + 1] + b1) * scale;
                if (MODE == 0) {
                    *reinterpret_cast<__half2*>((__half*)sOut + r * LDOUT + col) =
                        __floats2half2_rn(v0, v1);
                } else if (MODE == 1) {
                    ((__half*)sOut)[col * LDOUT + r]       = __float2half_rn(v0);
                    ((__half*)sOut)[(col + 1) * LDOUT + r] = __float2half_rn(v1);
                } else {
                    ((float*)sOut)[col * LDOUT + r]       = v0;
                    ((float*)sOut)[(col + 1) * LDOUT + r] = v1;
                }
            }
        }
}

// conflict-free staging: lane -> (4 channels x 8 tokens), 8-warp stride per window
template <int LDH>
__device__ __forceinline__ void stage_Xh(const float* __restrict__ img,
                                         __half* __restrict__ sX,
                                         int ch, int h0, int w0, int w8, int lane) {
    const int u = lane & 7;
    const int v = lane >> 3;
    for (int it = w8; it < ch * 2; it += 8) {
        const int cg = it >> 3, tg = it & 7;
        const int c = cg * 4 + v;
        const float val = img[(size_t)c * (IMG * IMG) + (size_t)(h0 + tg) * IMG + w0 + u];
        sX[(tg * 8 + u) * LDH + c] = __float2half_rn(val);
    }
}

__global__ void __launch_bounds__(THREADS, 1)
xswa_kernel(const float* __restrict__ xq, const float* __restrict__ xkv,
            const float* __restrict__ bq, const float* __restrict__ bk,
            const float* __restrict__ bv, const float* __restrict__ bias_table,
            const float* __restrict__ bo, float* __restrict__ out) {
    extern __shared__ char smc[];
    const int tid  = threadIdx.x;
    const int warp = tid >> 5;
    const int lane = tid & 31;
    const int g = lane >> 2, tig = lane & 3;
    const int wg = warp >> 3;      // window half 0/1
    const int w8 = warp & 7;       // local warp id

    const int win = blockIdx.x * 2 + wg;
    const int b   = win >> 10;
    const int rem = win & 1023;
    const int h0  = (rem >> 5) << 3;
    const int w0  = (rem & 31) << 3;

    char* wb = smc + wg * WBYTES;
    __half* sXKV = reinterpret_cast<__half*>(wb + WOFF_XKV);
    __half* sXQ  = reinterpret_cast<__half*>(wb + WOFF_XQ);
    __half* sQ   = reinterpret_cast<__half*>(wb + WOFF_Q);
    __half* sK   = reinterpret_cast<__half*>(wb + WOFF_K);
    __half* sVT  = reinterpret_cast<__half*>(wb + WOFF_VT);
    __half* sO   = sXQ;
    float*  sF   = reinterpret_cast<float*>(wb + WOFF_Q);
    float*  sBT  = reinterpret_cast<float*>(smc + OFF_BT);
    float*  sBQ  = reinterpret_cast<float*>(smc + OFF_BQ);
    float*  sBK  = reinterpret_cast<float*>(smc + OFF_BK);
    float*  sBV  = reinterpret_cast<float*>(smc + OFF_BV);
    float*  sBO  = reinterpret_cast<float*>(smc + OFF_BO);

    const float* xq_b  = xq  + (size_t)b * CQ  * (IMG * IMG);
    const float* xkv_b = xkv + (size_t)b * CKV * (IMG * IMG);

    // ---- stage (shared tables once, inputs per half), single full barrier ----
    for (int i = tid; i < 225 * NH; i += THREADS) sBT[i] = bias_table[i];
    if (tid < 96) {
        sBQ[tid] = bq[tid];
        sBK[tid] = bk[tid];
        sBV[tid] = bv[tid];
        sBO[tid] = bo[tid];
    }
    stage_Xh<LDH_X>(xkv_b, sXKV, CKV, h0, w0, w8, lane);
    stage_Xh<LDH_QK>(xq_b, sXQ, CQ, h0, w0, w8, lane);
    __syncthreads();

    // ---- projections: w8 0-3 K (m32n48), 4-7 V (m32n48); then Q all 8 (m16n48) ----
    if (w8 < 4) {
        gemm_h<2, 6, 6, LDH_X, 0, LDH_QK, false>(
            sXKV, gWF + FK_OFF, sBK, sK, 1.f, (w8 & 1) * 32, (w8 >> 1) * 6, lane);
    } else {
        const int w = w8 - 4;
        gemm_h<2, 6, 6, LDH_X, 1, LDH_VT, false>(
            sXKV, gWF + FV_OFF, sBV, sVT, 1.f, (w & 1) * 32, (w >> 1) * 6, lane);
    }
    gemm_h<1, 6, 3, LDH_QK, 0, LDH_QK, true>(
        sXQ, gWF + FQ_OFF, sBQ, sQ, 0.25f, (w8 & 3) * 16, (w8 >> 2) * 6, lane);
    barw(1 + wg);

    // ---- attention: 24 (head, m16) slices per window, 3 per warp ----
#pragma unroll
    for (int tt = 0; tt < 3; tt++) {
        const int slice = w8 * 3 + tt;
        const int head = slice >> 2;
        const int m0   = (slice & 3) * 16;

        // scores m16 x n64, k16
        float acc[8][4];
        {
            uint32_t Af[4];
            ldsm4(Af, smem_u32(sQ) + a_off16(m0, LDH_QK, lane) + head * 32);
#pragma unroll
            for (int nt = 0; nt < 8; nt++)
#pragma unroll
                for (int x = 0; x < 4; x++) acc[nt][x] = 0.f;
#pragma unroll
            for (int jn = 0; jn < 4; jn++) {
                uint32_t Bf[4];
                ldsm4(Bf, smem_u32(sK) + b_off16(jn * 16, LDH_QK, lane) + head * 32);
                mma16(acc[2 * jn],     Af, Bf[0], Bf[1]);
                mma16(acc[2 * jn + 1], Af, Bf[2], Bf[3]);
            }
        }

        // softmax in registers
        float rs0 = 0.f, rs1 = 0.f;
        {
            const int i0 = m0 + g, i1 = i0 + 8;
            const int ih0 = i0 >> 3, iw0 = i0 & 7;
            const int ih1 = i1 >> 3, iw1 = i1 & 7;
#pragma unroll
            for (int nt = 0; nt < 8; nt++) {
                const int j0 = nt * 8 + 2 * tig;
                const int jh0 = j0 >> 3, jw0 = j0 & 7;
                const int jh1 = (j0 + 1) >> 3, jw1 = (j0 + 1) & 7;
                acc[nt][0] = __expf(acc[nt][0] + sBT[((ih0 - jh0 + 7) * 15 + (iw0 - jw0 + 7)) * NH + head]);
                acc[nt][1] = __expf(acc[nt][1] + sBT[((ih0 - jh1 + 7) * 15 + (iw0 - jw1 + 7)) * NH + head]);
                acc[nt][2] = __expf(acc[nt][2] + sBT[((ih1 - jh0 + 7) * 15 + (iw1 - jw0 + 7)) * NH + head]);
                acc[nt][3] = __expf(acc[nt][3] + sBT[((ih1 - jh1 + 7) * 15 + (iw1 - jw1 + 7)) * NH + head]);
                rs0 += acc[nt][0] + acc[nt][1];
                rs1 += acc[nt][2] + acc[nt][3];
            }
            rs0 += __shfl_xor_sync(0xffffffffu, rs0, 1);
            rs0 += __shfl_xor_sync(0xffffffffu, rs0, 2);
            rs1 += __shfl_xor_sync(0xffffffffu, rs1, 1);
            rs1 += __shfl_xor_sync(0xffffffffu, rs1, 2);
            rs0 = 1.f / rs0;
            rs1 = 1.f / rs1;
        }

        // AV: k64 in 4 k16 chunks, A-frags packed from exp'd C regs
        float av[2][4];
#pragma unroll
        for (int j = 0; j < 2; j++)
#pragma unroll
            for (int x = 0; x < 4; x++) av[j][x] = 0.f;
        const uint32_t vb = smem_u32(sVT) + b_off16(head * 16, LDH_VT, lane);
#pragma unroll
        for (int j = 0; j < 4; j++) {
            uint32_t Bf[4];
            ldsm4(Bf, vb + j * 32);
            uint32_t af[4];
            af[0] = pack2(acc[2 * j][0],     acc[2 * j][1]);
            af[1] = pack2(acc[2 * j][2],     acc[2 * j][3]);
            af[2] = pack2(acc[2 * j + 1][0], acc[2 * j + 1][1]);
            af[3] = pack2(acc[2 * j + 1][2], acc[2 * j + 1][3]);
            mma16(av[0], af, Bf[0], Bf[1]);
            mma16(av[1], af, Bf[2], Bf[3]);
        }

        // normalize + write O (fp16, token-major)
#pragma unroll
        for (int j = 0; j < 2; j++) {
            const int col = head * 16 + j * 8 + 2 * tig;
            const int r0 = m0 + g;
            *reinterpret_cast<__half2*>(sO + r0 * LDH_QK + col) =
                __floats2half2_rn(av[j][0] * rs0, av[j][1] * rs0);
            *reinterpret_cast<__half2*>(sO + (r0 + 8) * LDH_QK + col) =
                __floats2half2_rn(av[j][2] * rs1, av[j][3] * rs1);
        }
    }
    barw(1 + wg);

    // ---- output projection: 8 warps m16n48 -> F fp32 [96][64] ----
    gemm_h<1, 6, 3, LDH_QK, 2, LD_F, true>(
        sO, gWF + FO_OFF, sBO, sF, 1.f, (w8 & 3) * 16, (w8 >> 2) * 6, lane);
    barw(1 + wg);

    // ---- coalesced store (per half, 256 threads) ----
    {
        const int t256 = tid & 255;
        float* out_b = out + (size_t)b * CQ * (IMG * IMG);
#pragma unroll
        for (int idx = t256; idx < CQ * WIN / 2; idx += 256) {
            const int c  = idx >> 5;
            const int t0 = (idx & 31) * 2;
            const float2 v = *reinterpret_cast<const float2*>(&sF[c * LD_F + t0]);
            float* dst = out_b + (size_t)c * (IMG * IMG)
                       + (size_t)(h0 + (t0 >> 3)) * IMG + (w0 + (t0 & 7));
            *reinterpret_cast<float2*>(dst) = v;
        }
    }
}

} // namespace

extern "C" void kernel_launch(void* const* d_in, const int* in_sizes, int n_in,
                              void* d_out, int out_size) {
    const float* xq   = (const float*)d_in[0];
    const float* xkv  = (const float*)d_in[1];
    const float* Wq   = (const float*)d_in[2];
    const float* bq   = (const float*)d_in[3];
    const float* Wk   = (const float*)d_in[4];
    const float* bk   = (const float*)d_in[5];
    const float* Wv   = (const float*)d_in[6];
    const float* bv   = (const float*)d_in[7];
    const float* bias_table = (const float*)d_in[8];
    const float* Wo   = (const float*)d_in[9];
    const float* bo   = (const float*)d_in[10];
    float* out = (float*)d_out;

    const int B = in_sizes[0] / (CQ * IMG * IMG);
    const int nwin = B * (IMG / 8) * (IMG / 8);

    prep_kernel<<<(F_TOTAL + 255) / 256, 256>>>(Wk, Wv, Wq, Wo);

    cudaFuncSetAttribute(xswa_kernel, cudaFuncAttributeMaxDynamicSharedMemorySize, SMEM_ALLOC);
    xswa_kernel<<<nwin / 2, THREADS, SMEM_ALLOC>>>(xq, xkv, bq, bk, bv,
                                                   bias_table, bo, out);
}